// round 6
// baseline (speedup 1.0000x reference)
#include <cuda_runtime.h>
#include <math.h>
#include <stdint.h>

// ---------------- problem constants ----------------
#define B_   32
#define CI   64
#define HH   128
#define WW   128
#define HW_  16384
#define OH   126
#define OW   126
#define CO   128
#define NCHK 8
#define CIC  8              // ci per chunk
#define TAPS 24             // 8 ci x 3 kh rows per chunk
#define KSTEPS 3            // 3 x k32 per 96 padded-k chunk
#define XT   33554432L

#define QXI    18.814814814814813f   // 127/6.75
#define DQX    0.05314960629921260f  // 6.75/127
#define MAGICF 12582912.0f           // 2^23 + 2^22

// ---------------- device scratch ----------------
__device__ int8_t g_w8[CO * 768];    // padded int8 weights [co][(ci*3+kh)*4+kw]
__device__ float  g_wdq[CO];         // per-co dequant scale (= wscale * DQX)
__device__ float  g_partial[B_ * OH * CO];

// ---------------- smem layout (bytes) ----------------
#define A_STRIDE 112
#define A0       128                  // tab (24 u32) lives below
#define A_BYTES  (128 * A_STRIDE)     // 14336
#define S1_0     (A0 + 2 * A_BYTES)   // 28800  fp32 staging
#define S1_STRIDE 544                 // 132 floats + pad
#define S1_BYTES (TAPS * S1_STRIDE)   // 13056
#define S2_0     (S1_0 + 2 * S1_BYTES)// 54912  int8 staging
#define S2_STRIDE 144
#define S2_BYTES (TAPS * S2_STRIDE)   // 3456
#define SMEM_DYN (S2_0 + S2_BYTES)    // 58368

// ---------------- helpers ----------------
__device__ __forceinline__ uint32_t smem_u32(const void* p) {
    uint32_t a;
    asm("{ .reg .u64 t; cvta.to.shared.u64 t, %1; cvt.u32.u64 %0, t; }" : "=r"(a) : "l"(p));
    return a;
}
__device__ __forceinline__ uint64_t to_global(const void* p) {
    uint64_t g;
    asm("cvta.to.global.u64 %0, %1;" : "=l"(g) : "l"(p));
    return g;
}
__device__ __forceinline__ float gelu_t(float v) {
    float u = 0.7978845608028654f * fmaf(0.044715f * v, v * v, v);
    float t;
    asm("tanh.approx.f32 %0, %1;" : "=f"(t) : "f"(u));
    return 0.5f * v * (1.0f + t);
}
__device__ __forceinline__ uint32_t lds32(uint32_t a) {
    uint32_t v;
    asm volatile("ld.shared.u32 %0, [%1];" : "=r"(v) : "r"(a));
    return v;
}
// read bytes [a8 + o .. +3] where o<8, from 12B window at 8-aligned a8
__device__ __forceinline__ uint32_t bwin(uint32_t a8, bool hiHalf, uint32_t sh) {
    uint32_t w0, w1, w2;
    asm volatile("ld.shared.v2.u32 {%0,%1}, [%2];" : "=r"(w0), "=r"(w1) : "r"(a8));
    asm volatile("ld.shared.u32 %0, [%1];" : "=r"(w2) : "r"(a8 + 8));
    uint32_t lo = hiHalf ? w1 : w0;
    uint32_t hi = hiHalf ? w2 : w1;
    return __funnelshift_r(lo, hi, sh);
}

#define CP16(dst, src) asm volatile("cp.async.ca.shared.global [%0], [%1], 16;" :: "r"(dst), "l"(src))
#define CP_COMMIT()    asm volatile("cp.async.commit_group;" ::: "memory")
#define CP_WAIT1()     asm volatile("cp.async.wait_group 1;" ::: "memory")
#define CP_WAIT0()     asm volatile("cp.async.wait_group 0;" ::: "memory")

#define MMA_S8(d, a, bb) \
    asm volatile("mma.sync.aligned.m16n8k32.row.col.s32.s8.s8.s32 " \
        "{%0,%1,%2,%3}, {%4,%5,%6,%7}, {%8,%9}, {%0,%1,%2,%3};" \
        : "+r"((d)[0]), "+r"((d)[1]), "+r"((d)[2]), "+r"((d)[3]) \
        : "r"((a)[0]), "r"((a)[1]), "r"((a)[2]), "r"((a)[3]), "r"((bb)[0]), "r"((bb)[1]))

// ---------------- weight quantization (per-co scale, padded kw->4) ----------------
__global__ void wq_kernel(const float* __restrict__ w)
{
    const int co = blockIdx.x;
    const int t  = threadIdx.x;   // 32 threads
    const float* wc = w + co * 576;
    float amax = 0.0f;
    for (int k = t; k < 576; k += 32) amax = fmaxf(amax, fabsf(wc[k]));
#pragma unroll
    for (int o = 16; o; o >>= 1) amax = fmaxf(amax, __shfl_xor_sync(~0u, amax, o));
    const float inv = 127.0f / amax;
    for (int k = t; k < 576; k += 32) {
        int ci = k / 9, r = k - 9 * ci, kh = r / 3, kw = r - 3 * kh;
        int q = __float2int_rn(wc[k] * inv);
        q = max(-127, min(127, q));
        g_w8[co * 768 + (ci * 3 + kh) * 4 + kw] = (int8_t)q;
    }
    for (int tap = t; tap < 192; tap += 32)
        g_w8[co * 768 + tap * 4 + 3] = 0;   // kw=3 pad
    if (t == 0) g_wdq[co] = (amax / 127.0f) * DQX;
}

// ---------------- main conv kernel ----------------
__global__ void __launch_bounds__(256, 2)
conv_mma_kernel(const float* __restrict__ x, const float* __restrict__ bias)
{
    extern __shared__ char smem[];
    const uint32_t sb = smem_u32(smem);
    const int tid = threadIdx.x;
    const int wid = tid >> 5;
    const int lane = tid & 31;
    const int oh = blockIdx.x;
    const int b  = blockIdx.y;

    // tap table: byte offset of (ci_local, kh) row within batch image
    uint32_t* tab = (uint32_t*)smem;
    if (tid < TAPS) {
        int ci = tid / 3, kh = tid - 3 * (tid / 3);
        tab[tid] = (uint32_t)((ci * HW_ + kh * WW) * 4);
    }

    const int mg = wid & 1;       // co 0-63 / 64-127
    const int ng = wid >> 1;      // 32-pos block
    const int g  = lane >> 2;
    const int c4 = lane & 3;

    int acc[4][4][4];
#pragma unroll
    for (int mf = 0; mf < 4; ++mf)
#pragma unroll
        for (int nf = 0; nf < 4; ++nf)
#pragma unroll
            for (int e = 0; e < 4; ++e) acc[mf][nf][e] = 0;

    const uint64_t gx    = to_global(x) + ((uint64_t)((long)b * CI * HW_ + (long)oh * WW)) * 4;
    const uint64_t gxlim = to_global(x) + (uint64_t)XT * 4 - 16;
    const uint64_t gw8   = to_global(g_w8);

    __syncthreads();   // tab visible

    auto load_chunk = [&](int c, int buf) {
        // A: int8 weights, 128 co x 96B  (768 CP16)
        const uint32_t aOff = sb + A0 + (uint32_t)buf * A_BYTES;
#pragma unroll
        for (int it = 0; it < 3; ++it) {
            int s = tid + it * 256;
            int co = s / 6, q = s - co * 6;
            CP16(aOff + co * A_STRIDE + q * 16,
                 gw8 + (uint64_t)co * 768 + c * 96 + q * 16);
        }
        // staging: 24 fp32 rows x 528B  (792 CP16)
        const uint32_t s1Off = sb + S1_0 + (uint32_t)buf * S1_BYTES;
        const uint64_t cAdd = (uint64_t)c * (CIC * HW_ * 4);
#pragma unroll
        for (int it = 0; it < 4; ++it) {
            int s = tid + it * 256;
            if (s < 792) {
                int row = s / 33, q = s - row * 33;
                uint32_t d = lds32(sb + row * 4);
                uint64_t src = gx + cAdd + d + (uint64_t)q * 16;
                src = (src > gxlim) ? gxlim : src;
                CP16(s1Off + row * S1_STRIDE + q * 16, src);
            }
        }
    };

    auto quant_chunk = [&](int buf) {
        const char* s1 = smem + S1_0 + buf * S1_BYTES;
#pragma unroll
        for (int it = 0; it < 4; ++it) {
            int s = tid + it * 256;
            if (s < 792) {
                int row = s / 33, q = s - row * 33;
                float4 v = *(const float4*)(s1 + row * S1_STRIDE + q * 16);
                uint32_t f0 = __float_as_uint(fmaf(v.x, QXI, MAGICF));
                uint32_t f1 = __float_as_uint(fmaf(v.y, QXI, MAGICF));
                uint32_t f2 = __float_as_uint(fmaf(v.z, QXI, MAGICF));
                uint32_t f3 = __float_as_uint(fmaf(v.w, QXI, MAGICF));
                uint32_t r01 = __byte_perm(f0, f1, 0x0040);
                uint32_t r23 = __byte_perm(f2, f3, 0x0040);
                uint32_t pk  = __byte_perm(r01, r23, 0x5410);
                *(uint32_t*)(smem + S2_0 + row * S2_STRIDE + q * 4) = pk;
            }
        }
    };

    load_chunk(0, 0); CP_COMMIT();
    load_chunk(1, 1); CP_COMMIT();

    // fragment addressing constants
    const uint32_t aBase = sb + A0 + (mg * 64 + g) * A_STRIDE + c4 * 4;
    const uint32_t bRow  = sb + S2_0 + c4 * S2_STRIDE;
    const uint32_t n0w   = (uint32_t)(ng * 32);
    const uint32_t shamt = 8u * (uint32_t)(g & 3);
    const bool hiHalf = (g >= 4);

#pragma unroll 1
    for (int cc = 0; cc < NCHK; ++cc) {
        if (cc < NCHK - 1) { CP_WAIT1(); } else { CP_WAIT0(); }
        __syncthreads();                 // stage1/A ready; prev MMA reads done

        quant_chunk(cc & 1);
        __syncthreads();                 // stage2 ready

        const uint32_t cur = (uint32_t)(cc & 1) * A_BYTES;
#pragma unroll
        for (int ks = 0; ks < KSTEPS; ++ks) {
            uint32_t afr[4][4];
#pragma unroll
            for (int mf = 0; mf < 4; ++mf) {
                uint32_t a = aBase + cur + mf * 16 * A_STRIDE + ks * 32;
                afr[mf][0] = lds32(a);
                afr[mf][1] = lds32(a + 8 * A_STRIDE);
                afr[mf][2] = lds32(a + 16);
                afr[mf][3] = lds32(a + 8 * A_STRIDE + 16);
            }
            uint32_t bfr[4][2];
#pragma unroll
            for (int nf = 0; nf < 4; ++nf) {
                uint32_t base = bRow + ks * (8 * S2_STRIDE) + n0w + nf * 8;
                bfr[nf][0] = bwin(base, hiHalf, shamt);
                bfr[nf][1] = bwin(base + 4 * S2_STRIDE, hiHalf, shamt);
            }
#pragma unroll
            for (int mf = 0; mf < 4; ++mf)
#pragma unroll
                for (int nf = 0; nf < 4; ++nf)
                    MMA_S8(acc[mf][nf], afr[mf], bfr[nf]);
        }
        __syncthreads();                 // MMA smem reads done before refill
        if (cc + 2 < NCHK) { load_chunk(cc + 2, cc & 1); CP_COMMIT(); }
    }

    // ---- epilogue: dequant + bias + gelu + pool (pos < 126) ----
    float* red = (float*)smem;           // 512 floats; tiles dead
    const int rr = lane >> 2;
    const int q  = lane & 3;
#pragma unroll
    for (int mf = 0; mf < 4; ++mf) {
#pragma unroll
        for (int half = 0; half < 2; ++half) {
            const int co = mg * 64 + mf * 16 + half * 8 + rr;
            const float dq = __ldg(&g_wdq[co]);
            const float bv = __ldg(bias + co);
            float s = 0.0f;
#pragma unroll
            for (int nf = 0; nf < 4; ++nf) {
#pragma unroll
                for (int e = 0; e < 2; ++e) {
                    const int pos = ng * 32 + nf * 8 + q * 2 + e;
                    const float v = fmaf((float)acc[mf][nf][half * 2 + e], dq, bv);
                    if (pos < OW) s += gelu_t(v);
                }
            }
            s += __shfl_xor_sync(0xFFFFFFFFu, s, 1);
            s += __shfl_xor_sync(0xFFFFFFFFu, s, 2);
            if (q == 0) red[ng * CO + co] = s;
        }
    }
    __syncthreads();
    if (tid < CO) {
        float s = red[tid] + red[CO + tid] + red[2 * CO + tid] + red[3 * CO + tid];
        g_partial[((long)b * OH + oh) * CO + tid] = s;
    }
}

// ---------------- final reduction ----------------
__global__ void reduce_kernel(float* __restrict__ out)
{
    __shared__ float sred[512];
    const int b   = blockIdx.x;
    const int co  = threadIdx.x & 127;
    const int seg = threadIdx.x >> 7;
    const float* p = g_partial + (long)b * OH * CO + co;
    const int o0 = seg * 32;
    const int o1 = (o0 + 32 < OH) ? (o0 + 32) : OH;
    float s = 0.0f;
    for (int t = o0; t < o1; ++t) s += p[t * CO];
    sred[threadIdx.x] = s;
    __syncthreads();
    if (threadIdx.x < 128) {
        float r = sred[threadIdx.x] + sred[threadIdx.x + 128]
                + sred[threadIdx.x + 256] + sred[threadIdx.x + 384];
        out[b * CO + threadIdx.x] = r * (1.0f / (float)(OH * OW));
    }
}

extern "C" void kernel_launch(void* const* d_in, const int* in_sizes, int n_in,
                              void* d_out, int out_size)
{
    const float* x      = (const float*)d_in[0];
    const float* weight = (const float*)d_in[1];
    const float* bias   = (const float*)d_in[2];
    float* out = (float*)d_out;

    cudaFuncSetAttribute(conv_mma_kernel,
                         cudaFuncAttributeMaxDynamicSharedMemorySize, SMEM_DYN);

    wq_kernel<<<128, 32>>>(weight);
    conv_mma_kernel<<<dim3(OH, B_), 256, SMEM_DYN>>>(x, bias);
    reduce_kernel<<<32, 512>>>(out);
}

// round 8
// speedup vs baseline: 1.3830x; 1.3830x over previous
#include <cuda_runtime.h>
#include <cuda_fp16.h>
#include <math.h>
#include <stdint.h>

// ---------------- problem constants ----------------
#define B_   32
#define CI   64
#define HH   128
#define WW   128
#define HW_  16384
#define OH   126
#define OW   126
#define CO   128
#define NT1  63              // valid tiles per dim
#define PTD  64              // padded tiles per dim
#define PTI  4096            // padded tiles per image (64x64)
#define TALL (B_ * PTI)      // 131072 total padded tiles
#define NCOMP 16

// ---------------- device scratch ----------------
__device__ __half g_U[NCOMP * CO * CI];        // 256 KB  [c][co][ci]
__device__ __half g_V[NCOMP * CI * TALL];      // 268 MB  [c][ci][T]
__device__ float  g_partial[(TALL / 32) * CO]; // 2 MB    [blk][co]

// ---------------- smem layout (wino_gemm) ----------------
#define A_STRIDE 144
#define A_BYTES  (CO * A_STRIDE)      // 18432
#define B_STRIDE 80
#define B_BYTES  (CI * B_STRIDE)      // 5120
#define B0_OFF   (2 * A_BYTES)        // 36864
#define SMEM_DYN (2 * A_BYTES + 2 * B_BYTES)  // 47104

// ---------------- helpers ----------------
__device__ __forceinline__ uint32_t smem_u32(const void* p) {
    uint32_t a;
    asm("{ .reg .u64 t; cvta.to.shared.u64 t, %1; cvt.u32.u64 %0, t; }" : "=r"(a) : "l"(p));
    return a;
}
__device__ __forceinline__ uint64_t to_global(const void* p) {
    uint64_t g;
    asm("cvta.to.global.u64 %0, %1;" : "=l"(g) : "l"(p));
    return g;
}
__device__ __forceinline__ float gelu_t(float v) {
    float u = 0.7978845608028654f * fmaf(0.044715f * v, v * v, v);
    float t;
    asm("tanh.approx.f32 %0, %1;" : "=f"(t) : "f"(u));
    return 0.5f * v * (1.0f + t);
}

#define CP16(dst, src) asm volatile("cp.async.ca.shared.global [%0], [%1], 16;" :: "r"(dst), "l"(src))
#define CP_COMMIT()    asm volatile("cp.async.commit_group;" ::: "memory")
#define CP_WAIT1()     asm volatile("cp.async.wait_group 1;" ::: "memory")
#define CP_WAIT0()     asm volatile("cp.async.wait_group 0;" ::: "memory")

#define LDSM_X4(r, a) \
    asm volatile("ldmatrix.sync.aligned.m8n8.x4.shared.b16 {%0,%1,%2,%3}, [%4];" \
        : "=r"((r)[0]), "=r"((r)[1]), "=r"((r)[2]), "=r"((r)[3]) : "r"(a))
#define LDSM_X2T(r, a) \
    asm volatile("ldmatrix.sync.aligned.m8n8.x2.trans.shared.b16 {%0,%1}, [%2];" \
        : "=r"((r)[0]), "=r"((r)[1]) : "r"(a))
#define MMA16816F(d, a, bb) \
    asm volatile("mma.sync.aligned.m16n8k16.row.col.f32.f16.f16.f32 " \
        "{%0,%1,%2,%3}, {%4,%5,%6,%7}, {%8,%9}, {%0,%1,%2,%3};" \
        : "+f"((d)[0]), "+f"((d)[1]), "+f"((d)[2]), "+f"((d)[3]) \
        : "r"((a)[0]), "r"((a)[1]), "r"((a)[2]), "r"((a)[3]), "r"((bb)[0]), "r"((bb)[1]))

// ---------------- U = G g G^T  (per co,ci) ----------------
__global__ void wu_kernel(const float* __restrict__ w)
{
    const int co = blockIdx.x;
    const int ci = threadIdx.x;
    const float* g = w + (co * CI + ci) * 9;
    float q[3][3];
#pragma unroll
    for (int r = 0; r < 3; ++r)
#pragma unroll
        for (int c = 0; c < 3; ++c) q[r][c] = g[r * 3 + c];
    float t[4][3];
#pragma unroll
    for (int c = 0; c < 3; ++c) {
        t[0][c] = q[0][c];
        t[1][c] = 0.5f * (q[0][c] + q[1][c] + q[2][c]);
        t[2][c] = 0.5f * (q[0][c] - q[1][c] + q[2][c]);
        t[3][c] = q[2][c];
    }
#pragma unroll
    for (int r = 0; r < 4; ++r) {
        float u0 = t[r][0];
        float u1 = 0.5f * (t[r][0] + t[r][1] + t[r][2]);
        float u2 = 0.5f * (t[r][0] - t[r][1] + t[r][2]);
        float u3 = t[r][2];
        g_U[((r * 4 + 0) * CO + co) * CI + ci] = __float2half(u0);
        g_U[((r * 4 + 1) * CO + co) * CI + ci] = __float2half(u1);
        g_U[((r * 4 + 2) * CO + co) * CI + ci] = __float2half(u2);
        g_U[((r * 4 + 3) * CO + co) * CI + ci] = __float2half(u3);
    }
}

// ---------------- V = B^T d B  (input transform) ----------------
__global__ void __launch_bounds__(256)
xf_kernel(const float* __restrict__ x)
{
    __shared__ float sx[20 * 128 + 8];   // +8 pad: tail tile-pair reads 2 floats past row 19
    const int s  = blockIdx.x;   // 0..7 (7 = pad row th=63)
    const int ci = blockIdx.y;
    const int b  = blockIdx.z;
    const int tid = threadIdx.x;

    if (s == 7) {   // zero th=63 pad row: T in [4032, 4096)
#pragma unroll
        for (int it = 0; it < 2; ++it) {
            int idx = tid + it * 256;           // 0..511
            int c = idx >> 5;
            int pr = idx & 31;
            size_t off = ((size_t)(c * CI + ci)) * TALL + (size_t)b * PTI + 4032 + pr * 2;
            *(uint32_t*)(g_V + off) = 0u;
        }
        return;
    }

    const float4* src = (const float4*)(x + ((size_t)(b * CI + ci) << 14) + 18 * s * 128);
#pragma unroll
    for (int it = 0; it < 3; ++it) {
        int idx = tid + it * 256;
        if (idx < 640) ((float4*)sx)[idx] = src[idx];
    }
    __syncthreads();

#pragma unroll
    for (int it = 0; it < 2; ++it) {
        int p = tid + it * 256;
        if (p < 288) {
            int thl = p >> 5;
            int twp = p & 31;
            int tw0 = twp * 2;
            float dd[4][6];
#pragma unroll
            for (int r = 0; r < 4; ++r) {
                const float* row = &sx[(thl * 2 + r) * 128 + tw0 * 2];
                float2 a0 = *(const float2*)(row);
                float2 a1 = *(const float2*)(row + 2);
                float2 a2 = *(const float2*)(row + 4);   // in-bounds via +8 pad
                dd[r][0] = a0.x; dd[r][1] = a0.y; dd[r][2] = a1.x;
                dd[r][3] = a1.y; dd[r][4] = a2.x; dd[r][5] = a2.y;
            }
            const bool v1 = (tw0 + 1) < NT1;
            float V0[16], V1[16];
#pragma unroll
            for (int tile = 0; tile < 2; ++tile) {
                const int o = tile * 2;
                float E[4][4];
#pragma unroll
                for (int r = 0; r < 4; ++r) {   // col transform within row
                    E[r][0] = dd[r][o + 0] - dd[r][o + 2];
                    E[r][1] = dd[r][o + 1] + dd[r][o + 2];
                    E[r][2] = dd[r][o + 2] - dd[r][o + 1];
                    E[r][3] = dd[r][o + 1] - dd[r][o + 3];
                }
                float* V = tile ? V1 : V0;
#pragma unroll
                for (int j = 0; j < 4; ++j) {   // row transform
                    V[0 * 4 + j] = E[0][j] - E[2][j];
                    V[1 * 4 + j] = E[1][j] + E[2][j];
                    V[2 * 4 + j] = E[2][j] - E[1][j];
                    V[3 * 4 + j] = E[1][j] - E[3][j];
                }
            }
            const int th = s * 9 + thl;
            const size_t tBase = (size_t)b * PTI + th * PTD + tw0;
#pragma unroll
            for (int c = 0; c < 16; ++c) {
                __half2 pk = __floats2half2_rn(V0[c], v1 ? V1[c] : 0.0f);
                size_t off = ((size_t)(c * CI + ci)) * TALL + tBase;
                *(uint32_t*)(g_V + off) = reinterpret_cast<uint32_t&>(pk);
            }
        }
    }
}

// ---------------- 16-component GEMM + output transform + pool ----------------
__global__ void __launch_bounds__(256, 2)
wino_gemm(const float* __restrict__ bias)
{
    extern __shared__ char smem[];
    const uint32_t sb = smem_u32(smem);
    const int tid  = threadIdx.x;
    const int wid  = tid >> 5;
    const int lane = tid & 31;
    const int mg = wid & 1;        // co half
    const int ng = wid >> 1;       // 8-tile group

    const uint32_t Tglob = blockIdx.x * 32;
    const uint64_t gU = to_global(g_U);
    const uint64_t gV = to_global(g_V) + (uint64_t)Tglob * 2;

    float y[4][4][4];   // [mf][el][q]
#pragma unroll
    for (int a = 0; a < 4; ++a)
#pragma unroll
        for (int e = 0; e < 4; ++e)
#pragma unroll
            for (int q = 0; q < 4; ++q) y[a][e][q] = 0.0f;

    auto load_comp = [&](int c, int buf) {
        const uint32_t aOff = sb + (uint32_t)buf * A_BYTES;
#pragma unroll
        for (int it = 0; it < 4; ++it) {
            int ss = tid + it * 256;
            int co = ss >> 3, q = ss & 7;
            CP16(aOff + co * A_STRIDE + q * 16,
                 gU + ((uint64_t)c << 14) + co * 128 + q * 16);
        }
        const uint32_t bOff = sb + B0_OFF + (uint32_t)buf * B_BYTES;
        {
            int row = tid >> 2, q = tid & 3;
            CP16(bOff + row * B_STRIDE + q * 16,
                 gV + ((uint64_t)(c * CI + row)) * (TALL * 2) + q * 16);
        }
    };

    load_comp(0, 0); CP_COMMIT();
    load_comp(1, 1); CP_COMMIT();

    const uint32_t aBase = sb + (mg * 64 + (lane & 15)) * A_STRIDE + (lane >> 4) * 16;
    const uint32_t bBase = sb + B0_OFF + (lane & 15) * B_STRIDE + ng * 16;

    constexpr float AT[2][4] = {{1.f, 1.f, 1.f, 0.f}, {0.f, 1.f, -1.f, -1.f}};

#pragma unroll
    for (int c = 0; c < NCOMP; ++c) {
        if (c < NCOMP - 2) { CP_WAIT1(); } else { CP_WAIT0(); }
        __syncthreads();

        const uint32_t curA = (uint32_t)(c & 1) * A_BYTES;
        const uint32_t curB = (uint32_t)(c & 1) * B_BYTES;

        float m[4][4];
#pragma unroll
        for (int mf = 0; mf < 4; ++mf)
#pragma unroll
            for (int e = 0; e < 4; ++e) m[mf][e] = 0.0f;

#pragma unroll
        for (int s = 0; s < 4; ++s) {
            uint32_t afr[4][4], bfr[2];
#pragma unroll
            for (int mf = 0; mf < 4; ++mf)
                LDSM_X4(afr[mf], aBase + curA + mf * 16 * A_STRIDE + s * 32);
            LDSM_X2T(bfr, bBase + curB + s * 16 * B_STRIDE);
#pragma unroll
            for (int mf = 0; mf < 4; ++mf)
                MMA16816F(m[mf], afr[mf], bfr);
        }
        __syncthreads();
        if (c + 2 < NCOMP) { load_comp(c + 2, c & 1); CP_COMMIT(); }

        // fold into output-transform accumulators (coeffs fold at compile time)
        const int cr = c >> 2, cc = c & 3;
#pragma unroll
        for (int mf = 0; mf < 4; ++mf)
#pragma unroll
            for (int e = 0; e < 4; ++e) {
                const float v = m[mf][e];
#pragma unroll
                for (int q = 0; q < 4; ++q) {
                    const float coef = AT[q >> 1][cr] * AT[q & 1][cc];
                    if (coef == 1.0f)       y[mf][e][q] += v;
                    else if (coef == -1.0f) y[mf][e][q] -= v;
                }
            }
    }

    // ---- epilogue: bias + gelu + pool over valid tiles ----
    float* red = (float*)smem;   // 512 floats (tiles dead)
    const int blkLoc = (int)(blockIdx.x & 127);   // 128 blocks per image
#pragma unroll
    for (int mf = 0; mf < 4; ++mf) {
#pragma unroll
        for (int half = 0; half < 2; ++half) {
            const int co = mg * 64 + mf * 16 + (lane >> 2) + half * 8;
            const float bv = __ldg(bias + co);
            float s = 0.0f;
#pragma unroll
            for (int e = 0; e < 2; ++e) {
                const int Timg = blkLoc * 32 + ng * 8 + (lane & 3) * 2 + e;
                const int th = Timg >> 6, tw = Timg & 63;
                if (th < NT1 && tw < NT1) {
#pragma unroll
                    for (int q = 0; q < 4; ++q)
                        s += gelu_t(y[mf][half * 2 + e][q] + bv);
                }
            }
            s += __shfl_xor_sync(0xFFFFFFFFu, s, 1);
            s += __shfl_xor_sync(0xFFFFFFFFu, s, 2);
            if ((lane & 3) == 0) red[ng * CO + co] = s;
        }
    }
    __syncthreads();
    if (tid < CO) {
        float s = red[tid] + red[CO + tid] + red[2 * CO + tid] + red[3 * CO + tid];
        g_partial[blockIdx.x * CO + tid] = s;
    }
}

// ---------------- final reduction ----------------
__global__ void reduce_kernel(float* __restrict__ out)
{
    __shared__ float sred[512];
    const int b   = blockIdx.x;
    const int co  = threadIdx.x & 127;
    const int seg = threadIdx.x >> 7;
    float s = 0.0f;
#pragma unroll
    for (int t = 0; t < 32; ++t) {
        int blk = seg * 32 + t;
        s += g_partial[(b * 128 + blk) * CO + co];
    }
    sred[threadIdx.x] = s;
    __syncthreads();
    if (threadIdx.x < 128) {
        float r = sred[threadIdx.x] + sred[threadIdx.x + 128]
                + sred[threadIdx.x + 256] + sred[threadIdx.x + 384];
        out[b * CO + threadIdx.x] = r * (1.0f / (float)(OH * OW));
    }
}

extern "C" void kernel_launch(void* const* d_in, const int* in_sizes, int n_in,
                              void* d_out, int out_size)
{
    const float* x      = (const float*)d_in[0];
    const float* weight = (const float*)d_in[1];
    const float* bias   = (const float*)d_in[2];
    float* out = (float*)d_out;

    cudaFuncSetAttribute(wino_gemm,
                         cudaFuncAttributeMaxDynamicSharedMemorySize, SMEM_DYN);

    wu_kernel<<<CO, CI>>>(weight);
    xf_kernel<<<dim3(8, CI, B_), 256>>>(x);
    wino_gemm<<<TALL / 32, 256, SMEM_DYN>>>(bias);
    reduce_kernel<<<B_, 512>>>(out);
}

// round 9
// speedup vs baseline: 2.3239x; 1.6803x over previous
#include <cuda_runtime.h>
#include <cuda_fp16.h>
#include <math.h>
#include <stdint.h>

// ---------------- problem constants ----------------
#define B_   32
#define CI   64
#define HH   128
#define WW   128
#define OH   126
#define OW   126
#define CO   128
#define NT1  63              // valid tiles per dim
#define PTD  64              // padded tiles per dim
#define PTI  4096            // padded tiles per image
#define TALL (B_ * PTI)      // 131072 padded tiles
#define NCOMP 16
#define NSTG  8              // 2 comps per stage

// ---------------- device scratch ----------------
__device__ __half g_U[NCOMP * CO * CI];        // 256 KB  [c][co][ci]
__device__ __half g_V[NCOMP * CI * TALL];      // 268 MB  [c][ci][T]
__device__ float  g_partial[B_ * NT1 * CO];    // [b][th][co]

// ---------------- smem layout (wino_gemm) ----------------
#define A_BYTES  18432                 // per comp: 128 co x 144B
#define B_BYTES  9216                  // per comp: 64 ci x 144B
#define STAGE    (2 * A_BYTES + 2 * B_BYTES)   // 55296
#define SMEM_DYN (2 * STAGE)                   // 110592

// ---------------- helpers ----------------
__device__ __forceinline__ uint32_t smem_u32(const void* p) {
    uint32_t a;
    asm("{ .reg .u64 t; cvta.to.shared.u64 t, %1; cvt.u32.u64 %0, t; }" : "=r"(a) : "l"(p));
    return a;
}
__device__ __forceinline__ uint64_t to_global(const void* p) {
    uint64_t g;
    asm("cvta.to.global.u64 %0, %1;" : "=l"(g) : "l"(p));
    return g;
}
__device__ __forceinline__ float gelu_t(float v) {
    float u = 0.7978845608028654f * fmaf(0.044715f * v, v * v, v);
    float t;
    asm("tanh.approx.f32 %0, %1;" : "=f"(t) : "f"(u));
    return 0.5f * v * (1.0f + t);
}

#define CP16(dst, src) asm volatile("cp.async.ca.shared.global [%0], [%1], 16;" :: "r"(dst), "l"(src))
#define CP_COMMIT()    asm volatile("cp.async.commit_group;" ::: "memory")
#define CP_WAIT1()     asm volatile("cp.async.wait_group 1;" ::: "memory")
#define CP_WAIT0()     asm volatile("cp.async.wait_group 0;" ::: "memory")

#define LDSM_X4(r, a) \
    asm volatile("ldmatrix.sync.aligned.m8n8.x4.shared.b16 {%0,%1,%2,%3}, [%4];" \
        : "=r"((r)[0]), "=r"((r)[1]), "=r"((r)[2]), "=r"((r)[3]) : "r"(a))
#define LDSM_X2T(r, a) \
    asm volatile("ldmatrix.sync.aligned.m8n8.x2.trans.shared.b16 {%0,%1}, [%2];" \
        : "=r"((r)[0]), "=r"((r)[1]) : "r"(a))
#define MMA16816F(d, a, bb) \
    asm volatile("mma.sync.aligned.m16n8k16.row.col.f32.f16.f16.f32 " \
        "{%0,%1,%2,%3}, {%4,%5,%6,%7}, {%8,%9}, {%0,%1,%2,%3};" \
        : "+f"((d)[0]), "+f"((d)[1]), "+f"((d)[2]), "+f"((d)[3]) \
        : "r"((a)[0]), "r"((a)[1]), "r"((a)[2]), "r"((a)[3]), "r"((bb)[0]), "r"((bb)[1]))

// ---------------- U = G g G^T ----------------
__global__ void wu_kernel(const float* __restrict__ w)
{
    const int co = blockIdx.x;
    const int ci = threadIdx.x;
    const float* g = w + (co * CI + ci) * 9;
    float q[3][3];
#pragma unroll
    for (int r = 0; r < 3; ++r)
#pragma unroll
        for (int c = 0; c < 3; ++c) q[r][c] = g[r * 3 + c];
    float t[4][3];
#pragma unroll
    for (int c = 0; c < 3; ++c) {
        t[0][c] = q[0][c];
        t[1][c] = 0.5f * (q[0][c] + q[1][c] + q[2][c]);
        t[2][c] = 0.5f * (q[0][c] - q[1][c] + q[2][c]);
        t[3][c] = q[2][c];
    }
#pragma unroll
    for (int r = 0; r < 4; ++r) {
        float u0 = t[r][0];
        float u1 = 0.5f * (t[r][0] + t[r][1] + t[r][2]);
        float u2 = 0.5f * (t[r][0] - t[r][1] + t[r][2]);
        float u3 = t[r][2];
        g_U[((r * 4 + 0) * CO + co) * CI + ci] = __float2half(u0);
        g_U[((r * 4 + 1) * CO + co) * CI + ci] = __float2half(u1);
        g_U[((r * 4 + 2) * CO + co) * CI + ci] = __float2half(u2);
        g_U[((r * 4 + 3) * CO + co) * CI + ci] = __float2half(u3);
    }
}

// ---------------- V = B^T d B ----------------
__global__ void __launch_bounds__(256)
xf_kernel(const float* __restrict__ x)
{
    __shared__ float sx[20 * 128 + 8];
    const int s  = blockIdx.x;   // 0..6
    const int ci = blockIdx.y;
    const int b  = blockIdx.z;
    const int tid = threadIdx.x;

    const float4* src = (const float4*)(x + ((size_t)(b * CI + ci) << 14) + 18 * s * 128);
#pragma unroll
    for (int it = 0; it < 3; ++it) {
        int idx = tid + it * 256;
        if (idx < 640) ((float4*)sx)[idx] = src[idx];
    }
    __syncthreads();

#pragma unroll
    for (int it = 0; it < 2; ++it) {
        int p = tid + it * 256;
        if (p < 288) {
            int thl = p >> 5;
            int twp = p & 31;
            int tw0 = twp * 2;
            float dd[4][6];
#pragma unroll
            for (int r = 0; r < 4; ++r) {
                const float* row = &sx[(thl * 2 + r) * 128 + tw0 * 2];
                float2 a0 = *(const float2*)(row);
                float2 a1 = *(const float2*)(row + 2);
                float2 a2 = *(const float2*)(row + 4);
                dd[r][0] = a0.x; dd[r][1] = a0.y; dd[r][2] = a1.x;
                dd[r][3] = a1.y; dd[r][4] = a2.x; dd[r][5] = a2.y;
            }
            const bool v1 = (tw0 + 1) < NT1;
            float V0[16], V1[16];
#pragma unroll
            for (int tile = 0; tile < 2; ++tile) {
                const int o = tile * 2;
                float E[4][4];
#pragma unroll
                for (int r = 0; r < 4; ++r) {
                    E[r][0] = dd[r][o + 0] - dd[r][o + 2];
                    E[r][1] = dd[r][o + 1] + dd[r][o + 2];
                    E[r][2] = dd[r][o + 2] - dd[r][o + 1];
                    E[r][3] = dd[r][o + 1] - dd[r][o + 3];
                }
                float* V = tile ? V1 : V0;
#pragma unroll
                for (int j = 0; j < 4; ++j) {
                    V[0 * 4 + j] = E[0][j] - E[2][j];
                    V[1 * 4 + j] = E[1][j] + E[2][j];
                    V[2 * 4 + j] = E[2][j] - E[1][j];
                    V[3 * 4 + j] = E[1][j] - E[3][j];
                }
            }
            const int th = s * 9 + thl;
            const size_t tBase = (size_t)b * PTI + th * PTD + tw0;
#pragma unroll
            for (int c = 0; c < 16; ++c) {
                __half2 pk = __floats2half2_rn(V0[c], v1 ? V1[c] : 0.0f);
                size_t off = ((size_t)(c * CI + ci)) * TALL + tBase;
                *(uint32_t*)(g_V + off) = reinterpret_cast<uint32_t&>(pk);
            }
        }
    }
}

// ---------------- GEMM + output transform + pool ----------------
__global__ void __launch_bounds__(512, 1)
wino_gemm(const float* __restrict__ bias)
{
    extern __shared__ char smem[];
    const uint32_t sb = smem_u32(smem);
    const int tid  = threadIdx.x;
    const int wid  = tid >> 5;
    const int lane = tid & 31;
    const int mg = wid & 1;        // co half
    const int ng = wid >> 1;       // 8-tile group (0..7)

    const int th = blockIdx.x;     // 0..62
    const int b  = blockIdx.y;
    const uint64_t gU = to_global(g_U);
    const uint64_t gV = to_global(g_V) + ((uint64_t)(b * PTI + th * PTD)) * 2;

    float y[4][4][4];
#pragma unroll
    for (int a = 0; a < 4; ++a)
#pragma unroll
        for (int e = 0; e < 4; ++e)
#pragma unroll
            for (int q = 0; q < 4; ++q) y[a][e][q] = 0.0f;

    auto load_stage = [&](int s, int buf) {
        const uint32_t st = sb + (uint32_t)buf * STAGE;
#pragma unroll
        for (int k = 0; k < 2; ++k) {
            const int c = 2 * s + k;
            const uint32_t aOff = st + (uint32_t)k * A_BYTES;
#pragma unroll
            for (int it = 0; it < 2; ++it) {
                int idx = tid + it * 512;
                int co = idx >> 3, q = idx & 7;
                CP16(aOff + co * 144 + q * 16,
                     gU + ((uint64_t)c << 14) + co * 128 + q * 16);
            }
            const uint32_t bOff = st + 2 * A_BYTES + (uint32_t)k * B_BYTES;
            int row = tid >> 3, q = tid & 7;
            CP16(bOff + row * 144 + q * 16,
                 gV + ((uint64_t)(c * CI + row)) * (TALL * 2) + q * 16);
        }
    };

    load_stage(0, 0); CP_COMMIT();
    load_stage(1, 1); CP_COMMIT();

    const uint32_t aBase = sb + (mg * 64 + (lane & 15)) * 144 + (lane >> 4) * 16;
    const uint32_t bBase = sb + 2 * A_BYTES + (lane & 15) * 144 + ng * 16;

#pragma unroll 1
    for (int s = 0; s < NSTG; ++s) {
        if (s < NSTG - 1) { CP_WAIT1(); } else { CP_WAIT0(); }
        __syncthreads();
        const uint32_t st = (uint32_t)(s & 1) * STAGE;

#pragma unroll
        for (int k = 0; k < 2; ++k) {
            const int c = 2 * s + k;
            const uint32_t curA = st + (uint32_t)k * A_BYTES;
            const uint32_t curB = st + (uint32_t)k * B_BYTES;

            float m[4][4];
#pragma unroll
            for (int mf = 0; mf < 4; ++mf)
#pragma unroll
                for (int e = 0; e < 4; ++e) m[mf][e] = 0.0f;

#pragma unroll
            for (int s4 = 0; s4 < 4; ++s4) {
                uint32_t afr[4][4], bfr[2];
#pragma unroll
                for (int mf = 0; mf < 4; ++mf)
                    LDSM_X4(afr[mf], aBase + curA + mf * 16 * 144 + s4 * 32);
                LDSM_X2T(bfr, bBase + curB + s4 * 16 * 144);
#pragma unroll
                for (int mf = 0; mf < 4; ++mf)
                    MMA16816F(m[mf], afr[mf], bfr);
            }

            // fold with select-computed coefficients (AT0={1,1,1,0}, AT1={0,1,-1,-1})
            const int cr = c >> 2, cc = c & 3;
            const float a0r = (cr < 3) ? 1.0f : 0.0f;
            const float a1r = (cr == 0) ? 0.0f : ((cr == 1) ? 1.0f : -1.0f);
            const float a0c = (cc < 3) ? 1.0f : 0.0f;
            const float a1c = (cc == 0) ? 0.0f : ((cc == 1) ? 1.0f : -1.0f);
            const float cq0 = a0r * a0c, cq1 = a0r * a1c;
            const float cq2 = a1r * a0c, cq3 = a1r * a1c;
#pragma unroll
            for (int mf = 0; mf < 4; ++mf)
#pragma unroll
                for (int e = 0; e < 4; ++e) {
                    const float v = m[mf][e];
                    y[mf][e][0] = fmaf(cq0, v, y[mf][e][0]);
                    y[mf][e][1] = fmaf(cq1, v, y[mf][e][1]);
                    y[mf][e][2] = fmaf(cq2, v, y[mf][e][2]);
                    y[mf][e][3] = fmaf(cq3, v, y[mf][e][3]);
                }
        }
        __syncthreads();
        if (s + 2 < NSTG) { load_stage(s + 2, s & 1); CP_COMMIT(); }
    }

    // ---- epilogue: bias + gelu + pool ----
    float* red = (float*)smem;     // 1024 floats (buffer 0 dead)
#pragma unroll
    for (int mf = 0; mf < 4; ++mf) {
#pragma unroll
        for (int half = 0; half < 2; ++half) {
            const int co = mg * 64 + mf * 16 + half * 8 + (lane >> 2);
            const float bv = __ldg(bias + co);
            float s = 0.0f;
#pragma unroll
            for (int e = 0; e < 2; ++e) {
                const int tw = ng * 8 + (lane & 3) * 2 + e;
                if (tw < NT1) {
#pragma unroll
                    for (int q = 0; q < 4; ++q)
                        s += gelu_t(y[mf][half * 2 + e][q] + bv);
                }
            }
            s += __shfl_xor_sync(0xFFFFFFFFu, s, 1);
            s += __shfl_xor_sync(0xFFFFFFFFu, s, 2);
            if ((lane & 3) == 0) red[ng * CO + co] = s;
        }
    }
    __syncthreads();
    if (tid < CO) {
        float t = 0.0f;
#pragma unroll
        for (int g = 0; g < 8; ++g) t += red[g * CO + tid];
        g_partial[(b * NT1 + th) * CO + tid] = t;
    }
}

// ---------------- final reduction ----------------
__global__ void reduce_kernel(float* __restrict__ out)
{
    __shared__ float sred[512];
    const int b   = blockIdx.x;
    const int co  = threadIdx.x & 127;
    const int seg = threadIdx.x >> 7;
    const int r0 = seg * 16;
    const int r1 = (seg == 3) ? NT1 : (r0 + 16);
    float s = 0.0f;
    for (int r = r0; r < r1; ++r)
        s += g_partial[(b * NT1 + r) * CO + co];
    sred[threadIdx.x] = s;
    __syncthreads();
    if (threadIdx.x < 128) {
        float r = sred[threadIdx.x] + sred[threadIdx.x + 128]
                + sred[threadIdx.x + 256] + sred[threadIdx.x + 384];
        out[b * CO + threadIdx.x] = r * (1.0f / (float)(OH * OW));
    }
}

extern "C" void kernel_launch(void* const* d_in, const int* in_sizes, int n_in,
                              void* d_out, int out_size)
{
    const float* x      = (const float*)d_in[0];
    const float* weight = (const float*)d_in[1];
    const float* bias   = (const float*)d_in[2];
    float* out = (float*)d_out;

    cudaFuncSetAttribute(wino_gemm,
                         cudaFuncAttributeMaxDynamicSharedMemorySize, SMEM_DYN);

    wu_kernel<<<CO, CI>>>(weight);
    xf_kernel<<<dim3(7, CI, B_), 256>>>(x);
    wino_gemm<<<dim3(NT1, B_), 512, SMEM_DYN>>>(bias);
    reduce_kernel<<<B_, 512>>>(out);
}